// round 8
// baseline (speedup 1.0000x reference)
#include <cuda_runtime.h>
#include <cuda_fp16.h>
#include <stdint.h>

#define BB 2
#define NH 8
#define TT 192
#define HD 64
#define CC 512
#define BH 16            // BB*NH
#define NTILE 6          // TT/32
#define NPAIR 21         // NTILE*(NTILE+1)/2
#define SCALE 0.125f     // 1/sqrt(64)
#define XN (BB*TT*CC)    // 196608
#define WN (CC*CC)       // 262144

// persistent device scratch (no allocations allowed)
__device__ __align__(16) float    g_q [BH*TT*HD];
__device__ __align__(16) float    g_k1[BH*TT*HD];
__device__ __align__(16) float    g_k2[BH*TT*HD];
__device__ __align__(16) float    g_Np[NTILE*BH*TT*HD];
__device__ __align__(16) float    g_Zp[BH*NPAIR];
__device__ __align__(16) unsigned g_xs[XN];        // x packed split-fp16
__device__ __align__(16) unsigned g_Ws[4][WN];     // W0,W1,W2,Wp packed
__device__ __align__(16) unsigned g_ys[XN];        // normalized y packed
__device__ __align__(16) float    g_outp[2][XN];   // out K-split partials

// ---------------------------------------------------------------------------
// HMMA helpers
__device__ __forceinline__ unsigned int pkh2(float a, float b)
{
    __half2 h = __floats2half2_rn(a, b);
    return *reinterpret_cast<unsigned int*>(&h);
}

__device__ __forceinline__ void mma16816(float* d, const unsigned int* a, const unsigned int* b)
{
    asm volatile(
        "mma.sync.aligned.m16n8k16.row.col.f32.f16.f16.f32 "
        "{%0,%1,%2,%3}, {%4,%5,%6,%7}, {%8,%9}, {%0,%1,%2,%3};\n"
        : "+f"(d[0]), "+f"(d[1]), "+f"(d[2]), "+f"(d[3])
        : "r"(a[0]), "r"(a[1]), "r"(a[2]), "r"(a[3]), "r"(b[0]), "r"(b[1]));
}

// pack value as (hi fp16) | (lo fp16 << 16); hi+lo ~ 22-bit mantissa of f
__device__ __forceinline__ unsigned int splitpack(float f)
{
    __half h = __float2half_rn(f);
    __half l = __float2half_rn(f - __half2float(h));
    return (unsigned int)__half_as_ushort(h) | ((unsigned int)__half_as_ushort(l) << 16);
}

// ---------------------------------------------------------------------------
// convert x + W0..W2 to packed split-fp16 (float4-vectorized)
__global__ __launch_bounds__(256)
void cvt_main(const float* __restrict__ x,  const float* __restrict__ W0,
              const float* __restrict__ W1, const float* __restrict__ W2)
{
    int i4 = (blockIdx.x * 256 + threadIdx.x) * 4;   // 960 blocks: XN + 3*WN
    const float* src;
    unsigned*    dst;
    if (i4 < XN) {
        src = x + i4;
        dst = g_xs + i4;
    } else {
        int o = i4 - XN;
        int r = o >> 18;          // WN = 2^18
        o &= (WN - 1);
        src = (r == 0 ? W0 : r == 1 ? W1 : W2) + o;
        dst = g_Ws[r] + o;
    }
    float4 v = *(const float4*)src;
    uint4 u;
    u.x = splitpack(v.x); u.y = splitpack(v.y);
    u.z = splitpack(v.z); u.w = splitpack(v.w);
    *(uint4*)dst = u;
}

// convert Wp (separate launch — shifts attn into the ncu-profiled slot)
__global__ __launch_bounds__(256)
void cvt_wp(const float* __restrict__ Wp)
{
    int i4 = (blockIdx.x * 256 + threadIdx.x) * 4;   // 256 blocks: WN
    float4 v = *(const float4*)(Wp + i4);
    uint4 u;
    u.x = splitpack(v.x); u.y = splitpack(v.y);
    u.z = splitpack(v.z); u.w = splitpack(v.w);
    *(uint4*)&g_Ws[3][i4] = u;
}

// ---------------------------------------------------------------------------
// split-fp16 GEMM core on pre-packed operands:
// C(64x64 @ row0,col0) += A(rows, packed) * B(rows, packed)^T over K [kb, ke)
// NOTE: smem row stride 68 uints (272B) keeps every row 16B-aligned for STS.128
__device__ __forceinline__ void gemm64_core(
    const unsigned* __restrict__ A, const unsigned* __restrict__ B,
    int row0, int col0, int kb, int ke, float (&acc)[2][2][4],
    unsigned (*sA)[68], unsigned (*sB)[68])
{
    const int tid = threadIdx.x;
    const int w  = tid >> 5, l = tid & 31;
    const int wm = w >> 2, wn = w & 3;
    const int g  = l >> 2, c2 = (l & 3) << 1;
    const int lr = tid >> 2, lc0 = (tid & 3) << 4;

    for (int kc = kb; kc < ke; kc += 64) {
        const unsigned* ap = A + (row0 + lr)*CC + kc + lc0;
        const unsigned* bp = B + (col0 + lr)*CC + kc + lc0;
        #pragma unroll
        for (int v = 0; v < 4; ++v) {
            *(uint4*)&sA[lr][lc0 + v*4] = *(const uint4*)(ap + v*4);
            *(uint4*)&sB[lr][lc0 + v*4] = *(const uint4*)(bp + v*4);
        }
        __syncthreads();
        #pragma unroll
        for (int ks = 0; ks < 4; ++ks) {
            const int k0 = ks*16 + c2;
            unsigned ahi[2][4], alo[2][4];
            #pragma unroll
            for (int mt = 0; mt < 2; ++mt) {
                const int r = wm*32 + mt*16 + g;
                uint2 p0 = *(const uint2*)&sA[r    ][k0    ];
                uint2 p1 = *(const uint2*)&sA[r + 8][k0    ];
                uint2 p2 = *(const uint2*)&sA[r    ][k0 + 8];
                uint2 p3 = *(const uint2*)&sA[r + 8][k0 + 8];
                ahi[mt][0] = __byte_perm(p0.x, p0.y, 0x5410);
                alo[mt][0] = __byte_perm(p0.x, p0.y, 0x7632);
                ahi[mt][1] = __byte_perm(p1.x, p1.y, 0x5410);
                alo[mt][1] = __byte_perm(p1.x, p1.y, 0x7632);
                ahi[mt][2] = __byte_perm(p2.x, p2.y, 0x5410);
                alo[mt][2] = __byte_perm(p2.x, p2.y, 0x7632);
                ahi[mt][3] = __byte_perm(p3.x, p3.y, 0x5410);
                alo[mt][3] = __byte_perm(p3.x, p3.y, 0x7632);
            }
            #pragma unroll
            for (int nt = 0; nt < 2; ++nt) {
                const int n = wn*16 + nt*8 + g;
                uint2 q0 = *(const uint2*)&sB[n][k0    ];
                uint2 q1 = *(const uint2*)&sB[n][k0 + 8];
                unsigned bhi[2], blo[2];
                bhi[0] = __byte_perm(q0.x, q0.y, 0x5410);
                blo[0] = __byte_perm(q0.x, q0.y, 0x7632);
                bhi[1] = __byte_perm(q1.x, q1.y, 0x5410);
                blo[1] = __byte_perm(q1.x, q1.y, 0x7632);
                #pragma unroll
                for (int mt = 0; mt < 2; ++mt) {
                    mma16816(acc[mt][nt], ahi[mt], bhi);
                    mma16816(acc[mt][nt], ahi[mt], blo);
                    mma16816(acc[mt][nt], alo[mt], bhi);
                }
            }
        }
        __syncthreads();
    }
}

// ---------------------------------------------------------------------------
// projections: q = x@W0^T, k1 = x@W1^T, k2 = x@W2^T, stored [bh][t][d]
__global__ __launch_bounds__(256)
void proj_kernel()
{
    __shared__ __align__(16) unsigned sA[64][68];
    __shared__ __align__(16) unsigned sB[64][68];
    float* dst = (blockIdx.z == 0) ? g_q : (blockIdx.z == 1) ? g_k1 : g_k2;
    const int row0 = blockIdx.y * 64, col0 = blockIdx.x * 64;
    float acc[2][2][4];
    #pragma unroll
    for (int a = 0; a < 2; ++a)
        #pragma unroll
        for (int b = 0; b < 2; ++b)
            #pragma unroll
            for (int c = 0; c < 4; ++c) acc[a][b][c] = 0.f;
    gemm64_core(g_xs, g_Ws[blockIdx.z], row0, col0, 0, CC, acc, sA, sB);

    const int w = threadIdx.x >> 5, l = threadIdx.x & 31;
    const int wm = w >> 2, wn = w & 3;
    #pragma unroll
    for (int mt = 0; mt < 2; ++mt)
        #pragma unroll
        for (int nt = 0; nt < 2; ++nt) {
            const int col = col0 + wn*16 + nt*8 + ((l & 3) << 1);
            const int h = col >> 6, d = col & 63;
            #pragma unroll
            for (int rh = 0; rh < 2; ++rh) {
                const int row = row0 + wm*32 + mt*16 + (l >> 2) + rh*8;
                const int b = row / TT, t = row - b*TT;
                float2 v = make_float2(acc[mt][nt][rh*2], acc[mt][nt][rh*2 + 1]);
                *(float2*)&dst[((b*NH + h)*TT + t)*HD + d] = v;
            }
        }
}

// ---------------------------------------------------------------------------
// one 32-token k-chunk, two-phase: (1) all MMAs into registers, (2) epilogues.
template<bool MJ, bool MK>
__device__ __forceinline__ void do_chunk(
    int n0, int ig, int j0, int g, int q2, int lane,
    const unsigned int (&afr)[2][4][4], const __half (*k2s)[72],
    float& zacc, float& nacc0, float& nacc1)
{
    float acc[4][2][4];

    // ---- phase 1: issue all MMAs (independent accumulator chains) ----
    #pragma unroll
    for (int nt = 0; nt < 4; ++nt) {
        if (MJ && MK && (n0 + nt*8) > ig) continue;
        const int tok = n0 + nt*8 + g;
        unsigned int bfr[4][2];
        #pragma unroll
        for (int ks = 0; ks < 4; ++ks) {
            bfr[ks][0] = *(const unsigned int*)&k2s[tok][ks*16 + q2];
            bfr[ks][1] = *(const unsigned int*)&k2s[tok][ks*16 + q2 + 8];
        }
        #pragma unroll
        for (int mt = 0; mt < 2; ++mt) {
            if (MJ && (j0 + mt*16) > ig) continue;
            acc[nt][mt][0] = acc[nt][mt][1] = acc[nt][mt][2] = acc[nt][mt][3] = 0.f;
            #pragma unroll
            for (int ks = 0; ks < 4; ++ks) mma16816(acc[nt][mt], afr[mt][ks], bfr[ks]);
        }
    }

    // ---- phase 2: exp + fold + PV per nt group ----
    #pragma unroll
    for (int nt = 0; nt < 4; ++nt) {
        if (MJ && MK && (n0 + nt*8) > ig) continue;
        float Qf0 = 0.f, Qf1 = 0.f;
        #pragma unroll
        for (int mt = 0; mt < 2; ++mt) {
            if (MJ && (j0 + mt*16) > ig) continue;
            const int jlo = j0 + mt*16 + g, jhi = jlo + 8;
            const int k0  = n0 + nt*8 + q2, k1 = k0 + 1;
            bool v0 = (!MJ || jlo <= ig) && (!MK || k0 <= jlo);
            bool v1 = (!MJ || jlo <= ig) && (!MK || k1 <= jlo);
            bool v2 = (!MJ || jhi <= ig) && (!MK || k0 <= jhi);
            bool v3 = (!MJ || jhi <= ig) && (!MK || k1 <= jhi);
            float p0 = v0 ? __expf(acc[nt][mt][0]*SCALE) : 0.f;
            float p1 = v1 ? __expf(acc[nt][mt][1]*SCALE) : 0.f;
            float p2 = v2 ? __expf(acc[nt][mt][2]*SCALE) : 0.f;
            float p3 = v3 ? __expf(acc[nt][mt][3]*SCALE) : 0.f;
            Qf0 += p0 + p2;
            Qf1 += p1 + p3;
        }
        // fold across the 8 j row-groups (lanes differing in bits 2..4)
        #pragma unroll
        for (int m = 4; m <= 16; m <<= 1) {
            Qf0 += __shfl_xor_sync(0xffffffffu, Qf0, m);
            Qf1 += __shfl_xor_sync(0xffffffffu, Qf1, m);
        }
        // Z post-fold: folded value replicated on 8 lanes -> weight by 1/8
        zacc += (Qf0 + Qf1) * 0.125f;
        // PV: broadcast folded (Qf0,Qf1) as one packed half2 per token-pair
        unsigned qp = pkh2(Qf0, Qf1);
        #pragma unroll
        for (int kk2 = 0; kk2 < 4; ++kk2) {
            unsigned u = __shfl_sync(0xffffffffu, qp, kk2);
            float2 qf = __half22float2(*reinterpret_cast<__half2*>(&u));
            const int t0 = n0 + nt*8 + kk2*2;
            float2 f0 = __half22float2(*(const __half2*)&k2s[t0    ][2*lane]);
            float2 f1 = __half22float2(*(const __half2*)&k2s[t0 + 1][2*lane]);
            nacc0 += qf.x*f0.x + qf.y*f1.x;
            nacc1 += qf.x*f0.y + qf.y*f1.y;
        }
    }
}

// ---------------------------------------------------------------------------
// fused trilinear scores (HMMA) + exp + j-fold + PV.
__global__ __launch_bounds__(256, 2)
void attn_kernel()
{
    __shared__ float  qs [32][65];
    __shared__ float  k1s[32][65];
    __shared__ __half k2s[192][72];
    __shared__ float  zred[8];

    const int bh = blockIdx.x & 15;
    const int p  = blockIdx.x >> 4;
    int tj = NTILE - 1, start = 0, cnt = 1;
    while (p >= start + cnt) { start += cnt; --tj; ++cnt; }
    const int ti = tj + (p - start);
    const int i0 = ti * 32, j0 = tj * 32;
    const int tid  = threadIdx.x;
    const int w    = tid >> 5, lane = tid & 31;
    const int g    = lane >> 2, q2 = (lane & 3) << 1;
    const bool diag = (ti == tj);

    {
        const float* qg  = g_q  + (bh*TT + i0)*HD;
        const float* k1g = g_k1 + (bh*TT + j0)*HD;
        for (int l = tid; l < 32*64; l += 256) {
            int r = l >> 6, d = l & 63;
            qs[r][d]  = qg[r*HD + d];
            k1s[r][d] = k1g[r*HD + d];
        }
        const int ntok = (tj + 1) * 32;
        const float* k2g = g_k2 + bh*TT*HD;
        for (int l = tid; l < ntok*16; l += 256) {
            int r = l >> 4, c4 = (l & 15) << 2;
            float4 v = *(const float4*)(k2g + r*HD + c4);
            *(__half2*)&k2s[r][c4]     = __floats2half2_rn(v.x, v.y);
            *(__half2*)&k2s[r][c4 + 2] = __floats2half2_rn(v.z, v.w);
        }
    }
    __syncthreads();

    float zacc = 0.f;

    for (int isub = 0; isub < 4; ++isub) {
        const int il = isub*8 + w;
        const int ig = i0 + il;

        unsigned int afr[2][4][4];
        #pragma unroll
        for (int mt = 0; mt < 2; ++mt) {
            const int jlo = mt*16 + g, jhi = jlo + 8;
            #pragma unroll
            for (int ks = 0; ks < 4; ++ks) {
                const int d0 = ks*16 + q2;
                float qa = qs[il][d0],   qb = qs[il][d0+1];
                float qc = qs[il][d0+8], qd = qs[il][d0+9];
                afr[mt][ks][0] = pkh2(qa*k1s[jlo][d0],   qb*k1s[jlo][d0+1]);
                afr[mt][ks][1] = pkh2(qa*k1s[jhi][d0],   qb*k1s[jhi][d0+1]);
                afr[mt][ks][2] = pkh2(qc*k1s[jlo][d0+8], qd*k1s[jlo][d0+9]);
                afr[mt][ks][3] = pkh2(qc*k1s[jhi][d0+8], qd*k1s[jhi][d0+9]);
            }
        }

        float nacc0 = 0.f, nacc1 = 0.f;
        for (int kc = 0; kc <= tj; ++kc) {
            const int n0 = kc * 32;
            const bool mk = (kc == tj);
            if (diag) {
                if (mk) do_chunk<true ,true >(n0, ig, j0, g, q2, lane, afr, k2s, zacc, nacc0, nacc1);
                else    do_chunk<true ,false>(n0, ig, j0, g, q2, lane, afr, k2s, zacc, nacc0, nacc1);
            } else {
                if (mk) do_chunk<false,true >(n0, ig, j0, g, q2, lane, afr, k2s, zacc, nacc0, nacc1);
                else    do_chunk<false,false>(n0, ig, j0, g, q2, lane, afr, k2s, zacc, nacc0, nacc1);
            }
        }
        float* np = g_Np + ((tj*BH + bh)*TT + ig)*HD + 2*lane;
        np[0] = nacc0;
        np[1] = nacc1;
    }

    #pragma unroll
    for (int m = 16; m >= 1; m >>= 1)
        zacc += __shfl_xor_sync(0xffffffffu, zacc, m);
    if (lane == 0) zred[w] = zacc;
    __syncthreads();
    if (tid == 0) {
        float z = 0.f;
        #pragma unroll
        for (int ww = 0; ww < 8; ++ww) z += zred[ww];
        g_Zp[bh*NPAIR + p] = z;
    }
}

// ---------------------------------------------------------------------------
// y = (sum of valid slab partials)/Z, written PACKED split-fp16 for out GEMM
__global__ __launch_bounds__(256)
void finalize_y()
{
    __shared__ float invZ[BH];
    const int tid = threadIdx.x;
    if (tid < BH) {
        float z = 0.f;
        #pragma unroll
        for (int pp = 0; pp < NPAIR; ++pp) z += g_Zp[tid*NPAIR + pp];
        invZ[tid] = 1.f / z;
    }
    __syncthreads();
    int e  = blockIdx.x * 256 + tid;    // < XN/4 = 49152
    int c4 = e & 127;
    int r  = e >> 7;
    int b = r / TT, t = r - b*TT;
    int h = c4 >> 4, d4 = c4 & 15;
    int bh = b*NH + h;
    float4 acc = make_float4(0.f, 0.f, 0.f, 0.f);
    const int smax = t >> 5;
    #pragma unroll
    for (int s = 0; s < NTILE; ++s) {      // unrolled + predicated -> MLP 6
        if (s <= smax) {
            float4 v = *(const float4*)&g_Np[((s*BH + bh)*TT + t)*HD + d4*4];
            acc.x += v.x; acc.y += v.y; acc.z += v.z; acc.w += v.w;
        }
    }
    float iz = invZ[bh];
    uint4 u;
    u.x = splitpack(acc.x * iz); u.y = splitpack(acc.y * iz);
    u.z = splitpack(acc.z * iz); u.w = splitpack(acc.w * iz);
    *(uint4*)&g_ys[r*CC + c4*4] = u;
}

// ---------------------------------------------------------------------------
// out partials: K-split halves of y @ Wp^T
__global__ __launch_bounds__(256)
void out_kernel()
{
    __shared__ __align__(16) unsigned sA[64][68];
    __shared__ __align__(16) unsigned sB[64][68];
    const int row0 = blockIdx.y * 64, col0 = blockIdx.x * 64;
    const int z = blockIdx.z;
    float acc[2][2][4];
    #pragma unroll
    for (int a = 0; a < 2; ++a)
        #pragma unroll
        for (int b = 0; b < 2; ++b)
            #pragma unroll
            for (int c = 0; c < 4; ++c) acc[a][b][c] = 0.f;
    gemm64_core(g_ys, g_Ws[3], row0, col0, z*(CC/2), (z+1)*(CC/2), acc, sA, sB);

    const int w = threadIdx.x >> 5, l = threadIdx.x & 31;
    const int wm = w >> 2, wn = w & 3;
    float* op = g_outp[z];
    #pragma unroll
    for (int mt = 0; mt < 2; ++mt)
        #pragma unroll
        for (int nt = 0; nt < 2; ++nt) {
            const int col = col0 + wn*16 + nt*8 + ((l & 3) << 1);
            #pragma unroll
            for (int rh = 0; rh < 2; ++rh) {
                const int row = row0 + wm*32 + mt*16 + (l >> 2) + rh*8;
                float2 v = make_float2(acc[mt][nt][rh*2], acc[mt][nt][rh*2 + 1]);
                *(float2*)&op[row*CC + col] = v;
            }
        }
}

// ---------------------------------------------------------------------------
__global__ __launch_bounds__(256)
void reduce_out(float* __restrict__ out)
{
    int e4 = (blockIdx.x * 256 + threadIdx.x) * 4;   // < XN
    float4 a = *(const float4*)&g_outp[0][e4];
    float4 b = *(const float4*)&g_outp[1][e4];
    float4 r = make_float4(a.x + b.x, a.y + b.y, a.z + b.z, a.w + b.w);
    *(float4*)&out[e4] = r;
}

// ---------------------------------------------------------------------------
extern "C" void kernel_launch(void* const* d_in, const int* in_sizes, int n_in,
                              void* d_out, int out_size)
{
    const float* x  = (const float*)d_in[0];
    const float* W0 = (const float*)d_in[1];
    const float* W1 = (const float*)d_in[2];
    const float* W2 = (const float*)d_in[3];
    const float* Wp = (const float*)d_in[4];
    float* out = (float*)d_out;

    cvt_main<<<(XN + 3*WN)/(256*4), 256>>>(x, W0, W1, W2);     // launch 1
    cvt_wp<<<WN/(256*4), 256>>>(Wp);                            // launch 2
    dim3 pg(CC/64, (BB*TT)/64, 3);
    proj_kernel<<<pg, 256>>>();                                 // launch 3
    attn_kernel<<<NPAIR*BH, 256>>>();                           // launch 4 (profiled)
    finalize_y<<<(XN/4)/256, 256>>>();
    dim3 og(CC/64, (BB*TT)/64, 2);
    out_kernel<<<og, 256>>>();
    reduce_out<<<(XN/4)/256, 256>>>(out);
}

// round 9
// speedup vs baseline: 1.1140x; 1.1140x over previous
#include <cuda_runtime.h>
#include <cuda_fp16.h>
#include <stdint.h>

#define BB 2
#define NH 8
#define TT 192
#define HD 64
#define CC 512
#define BH 16            // BB*NH
#define NTILE 6          // TT/32
#define NPAIR 21         // NTILE*(NTILE+1)/2
#define QPRE 0.18033688f // 0.125 * log2(e): exp(S/8) = exp2(S*QPRE)
#define XN (BB*TT*CC)    // 196608
#define WN (CC*CC)       // 262144

// attn dynamic smem layout (bytes)
#define SM_K2S   0                       // __half[192][72] = 27648
#define SM_QS    27648                   // float [32][65]  = 8320
#define SM_K1S   35968                   // float [32][65]  = 8320
#define SM_QTAB  44288                   // __half[32][200] = 12800
#define SM_ZRED  57088                   // float[8]        = 32
#define SM_ATTN  57344

// persistent device scratch (no allocations allowed)
__device__ __align__(16) float    g_q [BH*TT*HD];
__device__ __align__(16) float    g_k1[BH*TT*HD];
__device__ __align__(16) float    g_k2[BH*TT*HD];
__device__ __align__(16) float    g_Np[NTILE*BH*TT*HD];
__device__ __align__(16) float    g_Zp[BH*NPAIR];
__device__ __align__(16) unsigned g_xs[XN];        // x packed split-fp16
__device__ __align__(16) unsigned g_Ws[4][WN];     // W0,W1,W2,Wp packed
__device__ __align__(16) unsigned g_ys[XN];        // normalized y packed
__device__ __align__(16) float    g_outp[2][XN];   // out K-split partials

// ---------------------------------------------------------------------------
// HMMA helpers
__device__ __forceinline__ unsigned int pkh2(float a, float b)
{
    __half2 h = __floats2half2_rn(a, b);
    return *reinterpret_cast<unsigned int*>(&h);
}

__device__ __forceinline__ void mma16816(float* d, const unsigned int* a, const unsigned int* b)
{
    asm volatile(
        "mma.sync.aligned.m16n8k16.row.col.f32.f16.f16.f32 "
        "{%0,%1,%2,%3}, {%4,%5,%6,%7}, {%8,%9}, {%0,%1,%2,%3};\n"
        : "+f"(d[0]), "+f"(d[1]), "+f"(d[2]), "+f"(d[3])
        : "r"(a[0]), "r"(a[1]), "r"(a[2]), "r"(a[3]), "r"(b[0]), "r"(b[1]));
}

__device__ __forceinline__ void ldsm_x2_trans(unsigned& r0, unsigned& r1, unsigned addr)
{
    asm volatile("ldmatrix.sync.aligned.m8n8.x2.trans.shared.b16 {%0,%1}, [%2];"
        : "=r"(r0), "=r"(r1) : "r"(addr));
}

__device__ __forceinline__ unsigned su32(const void* p)
{
    return (unsigned)__cvta_generic_to_shared(p);
}

// pack value as (hi fp16) | (lo fp16 << 16); hi+lo ~ 22-bit mantissa of f
__device__ __forceinline__ unsigned int splitpack(float f)
{
    __half h = __float2half_rn(f);
    __half l = __float2half_rn(f - __half2float(h));
    return (unsigned int)__half_as_ushort(h) | ((unsigned int)__half_as_ushort(l) << 16);
}

// ---------------------------------------------------------------------------
// convert x + W0..W2 to packed split-fp16 (float4-vectorized)
__global__ __launch_bounds__(256)
void cvt_main(const float* __restrict__ x,  const float* __restrict__ W0,
              const float* __restrict__ W1, const float* __restrict__ W2)
{
    int i4 = (blockIdx.x * 256 + threadIdx.x) * 4;   // 960 blocks: XN + 3*WN
    const float* src;
    unsigned*    dst;
    if (i4 < XN) {
        src = x + i4;
        dst = g_xs + i4;
    } else {
        int o = i4 - XN;
        int r = o >> 18;          // WN = 2^18
        o &= (WN - 1);
        src = (r == 0 ? W0 : r == 1 ? W1 : W2) + o;
        dst = g_Ws[r] + o;
    }
    float4 v = *(const float4*)src;
    uint4 u;
    u.x = splitpack(v.x); u.y = splitpack(v.y);
    u.z = splitpack(v.z); u.w = splitpack(v.w);
    *(uint4*)dst = u;
}

// convert Wp (separate launch — keeps attn in the ncu-profiled slot #4)
__global__ __launch_bounds__(256)
void cvt_wp(const float* __restrict__ Wp)
{
    int i4 = (blockIdx.x * 256 + threadIdx.x) * 4;   // 256 blocks: WN
    float4 v = *(const float4*)(Wp + i4);
    uint4 u;
    u.x = splitpack(v.x); u.y = splitpack(v.y);
    u.z = splitpack(v.z); u.w = splitpack(v.w);
    *(uint4*)&g_Ws[3][i4] = u;
}

// ---------------------------------------------------------------------------
// split-fp16 GEMM core on pre-packed operands (row stride 68 = 16B-aligned rows)
__device__ __forceinline__ void gemm64_core(
    const unsigned* __restrict__ A, const unsigned* __restrict__ B,
    int row0, int col0, int kb, int ke, float (&acc)[2][2][4],
    unsigned (*sA)[68], unsigned (*sB)[68])
{
    const int tid = threadIdx.x;
    const int w  = tid >> 5, l = tid & 31;
    const int wm = w >> 2, wn = w & 3;
    const int g  = l >> 2, c2 = (l & 3) << 1;
    const int lr = tid >> 2, lc0 = (tid & 3) << 4;

    for (int kc = kb; kc < ke; kc += 64) {
        const unsigned* ap = A + (row0 + lr)*CC + kc + lc0;
        const unsigned* bp = B + (col0 + lr)*CC + kc + lc0;
        #pragma unroll
        for (int v = 0; v < 4; ++v) {
            *(uint4*)&sA[lr][lc0 + v*4] = *(const uint4*)(ap + v*4);
            *(uint4*)&sB[lr][lc0 + v*4] = *(const uint4*)(bp + v*4);
        }
        __syncthreads();
        #pragma unroll
        for (int ks = 0; ks < 4; ++ks) {
            const int k0 = ks*16 + c2;
            unsigned ahi[2][4], alo[2][4];
            #pragma unroll
            for (int mt = 0; mt < 2; ++mt) {
                const int r = wm*32 + mt*16 + g;
                uint2 p0 = *(const uint2*)&sA[r    ][k0    ];
                uint2 p1 = *(const uint2*)&sA[r + 8][k0    ];
                uint2 p2 = *(const uint2*)&sA[r    ][k0 + 8];
                uint2 p3 = *(const uint2*)&sA[r + 8][k0 + 8];
                ahi[mt][0] = __byte_perm(p0.x, p0.y, 0x5410);
                alo[mt][0] = __byte_perm(p0.x, p0.y, 0x7632);
                ahi[mt][1] = __byte_perm(p1.x, p1.y, 0x5410);
                alo[mt][1] = __byte_perm(p1.x, p1.y, 0x7632);
                ahi[mt][2] = __byte_perm(p2.x, p2.y, 0x5410);
                alo[mt][2] = __byte_perm(p2.x, p2.y, 0x7632);
                ahi[mt][3] = __byte_perm(p3.x, p3.y, 0x5410);
                alo[mt][3] = __byte_perm(p3.x, p3.y, 0x7632);
            }
            #pragma unroll
            for (int nt = 0; nt < 2; ++nt) {
                const int n = wn*16 + nt*8 + g;
                uint2 q0 = *(const uint2*)&sB[n][k0    ];
                uint2 q1 = *(const uint2*)&sB[n][k0 + 8];
                unsigned bhi[2], blo[2];
                bhi[0] = __byte_perm(q0.x, q0.y, 0x5410);
                blo[0] = __byte_perm(q0.x, q0.y, 0x7632);
                bhi[1] = __byte_perm(q1.x, q1.y, 0x5410);
                blo[1] = __byte_perm(q1.x, q1.y, 0x7632);
                #pragma unroll
                for (int mt = 0; mt < 2; ++mt) {
                    mma16816(acc[mt][nt], ahi[mt], bhi);
                    mma16816(acc[mt][nt], ahi[mt], blo);
                    mma16816(acc[mt][nt], alo[mt], bhi);
                }
            }
        }
        __syncthreads();
    }
}

// ---------------------------------------------------------------------------
// projections: q = x@W0^T, k1 = x@W1^T, k2 = x@W2^T, stored [bh][t][d]
__global__ __launch_bounds__(256)
void proj_kernel()
{
    __shared__ __align__(16) unsigned sA[64][68];
    __shared__ __align__(16) unsigned sB[64][68];
    float* dst = (blockIdx.z == 0) ? g_q : (blockIdx.z == 1) ? g_k1 : g_k2;
    const int row0 = blockIdx.y * 64, col0 = blockIdx.x * 64;
    float acc[2][2][4];
    #pragma unroll
    for (int a = 0; a < 2; ++a)
        #pragma unroll
        for (int b = 0; b < 2; ++b)
            #pragma unroll
            for (int c = 0; c < 4; ++c) acc[a][b][c] = 0.f;
    gemm64_core(g_xs, g_Ws[blockIdx.z], row0, col0, 0, CC, acc, sA, sB);

    const int w = threadIdx.x >> 5, l = threadIdx.x & 31;
    const int wm = w >> 2, wn = w & 3;
    #pragma unroll
    for (int mt = 0; mt < 2; ++mt)
        #pragma unroll
        for (int nt = 0; nt < 2; ++nt) {
            const int col = col0 + wn*16 + nt*8 + ((l & 3) << 1);
            const int h = col >> 6, d = col & 63;
            #pragma unroll
            for (int rh = 0; rh < 2; ++rh) {
                const int row = row0 + wm*32 + mt*16 + (l >> 2) + rh*8;
                const int b = row / TT, t = row - b*TT;
                float2 v = make_float2(acc[mt][nt][rh*2], acc[mt][nt][rh*2 + 1]);
                *(float2*)&dst[((b*NH + h)*TT + t)*HD + d] = v;
            }
        }
}

// ---------------------------------------------------------------------------
// one 32-token k-chunk: score MMA + exp2 + j-fold -> Qs smem row (no PV here).
template<bool MJ, bool MK>
__device__ __forceinline__ void do_chunk(
    int n0, int ig, int il, int j0, int g, int q2, int lane,
    const unsigned (&afr)[2][4][4], const __half (*k2s)[72],
    __half (*Qtab)[200], float& zacc)
{
    #pragma unroll
    for (int nt = 0; nt < 4; ++nt) {
        if (MJ && MK && (n0 + nt*8) > ig) continue;   // fully-masked token group
        const int tok = n0 + nt*8 + g;
        unsigned bfr[4][2];
        #pragma unroll
        for (int ks = 0; ks < 4; ++ks) {
            bfr[ks][0] = *(const unsigned*)&k2s[tok][ks*16 + q2];
            bfr[ks][1] = *(const unsigned*)&k2s[tok][ks*16 + q2 + 8];
        }
        float Qf0 = 0.f, Qf1 = 0.f;
        #pragma unroll
        for (int mt = 0; mt < 2; ++mt) {
            if (MJ && (j0 + mt*16) > ig) continue;    // whole 16-row group above i
            float acc[4] = {0.f, 0.f, 0.f, 0.f};
            #pragma unroll
            for (int ks = 0; ks < 4; ++ks) mma16816(acc, afr[mt][ks], bfr[ks]);
            const int jlo = j0 + mt*16 + g, jhi = jlo + 8;
            const int k0  = n0 + nt*8 + q2, k1 = k0 + 1;
            bool v0 = (!MJ || jlo <= ig) && (!MK || k0 <= jlo);
            bool v1 = (!MJ || jlo <= ig) && (!MK || k1 <= jlo);
            bool v2 = (!MJ || jhi <= ig) && (!MK || k0 <= jhi);
            bool v3 = (!MJ || jhi <= ig) && (!MK || k1 <= jhi);
            float p0 = v0 ? exp2f(acc[0]) : 0.f;      // scale pre-folded into q
            float p1 = v1 ? exp2f(acc[1]) : 0.f;
            float p2 = v2 ? exp2f(acc[2]) : 0.f;
            float p3 = v3 ? exp2f(acc[3]) : 0.f;
            Qf0 += p0 + p2;
            Qf1 += p1 + p3;
        }
        // fold across the 8 j row-groups (lanes differing in bits 2..4)
        #pragma unroll
        for (int m = 4; m <= 16; m <<= 1) {
            Qf0 += __shfl_xor_sync(0xffffffffu, Qf0, m);
            Qf1 += __shfl_xor_sync(0xffffffffu, Qf1, m);
        }
        zacc += (Qf0 + Qf1) * 0.125f;                 // 8-lane replication
        unsigned qp = pkh2(Qf0, Qf1);
        if (lane < 4)                                  // lanes 0..3 cover 8 tokens
            *(unsigned*)&Qtab[il][n0 + nt*8 + (lane << 1)] = qp;
    }
}

// ---------------------------------------------------------------------------
// fused trilinear scores (HMMA) + exp + j-fold -> Qs; PV as one block GEMM.
__global__ __launch_bounds__(256, 3)
void attn_kernel()
{
    extern __shared__ char dynsm[];
    __half (*k2s)[72]  = (__half(*)[72]) (dynsm + SM_K2S);
    float  (*qs)[65]   = (float(*)[65])  (dynsm + SM_QS);
    float  (*k1s)[65]  = (float(*)[65])  (dynsm + SM_K1S);
    __half (*Qtab)[200]= (__half(*)[200])(dynsm + SM_QTAB);
    float* zred        = (float*)        (dynsm + SM_ZRED);

    const int bh = blockIdx.x & 15;
    const int p  = blockIdx.x >> 4;
    int tj = NTILE - 1, start = 0, cnt = 1;
    while (p >= start + cnt) { start += cnt; --tj; ++cnt; }
    const int ti = tj + (p - start);
    const int i0 = ti * 32, j0 = tj * 32;
    const int tid  = threadIdx.x;
    const int w    = tid >> 5, lane = tid & 31;
    const int g    = lane >> 2, q2 = (lane & 3) << 1;
    const bool diag = (ti == tj);
    const int K = (tj + 1) * 32;

    // load q (prescaled by QPRE) / k1 fp32; k2 fp16; zero Qtab
    {
        const float* qg  = g_q  + (bh*TT + i0)*HD;
        const float* k1g = g_k1 + (bh*TT + j0)*HD;
        for (int l = tid; l < 32*64; l += 256) {
            int r = l >> 6, d = l & 63;
            qs[r][d]  = qg[r*HD + d] * QPRE;
            k1s[r][d] = k1g[r*HD + d];
        }
        const float* k2g = g_k2 + bh*TT*HD;
        for (int l = tid; l < K*16; l += 256) {
            int r = l >> 4, c4 = (l & 15) << 2;
            float4 v = *(const float4*)(k2g + r*HD + c4);
            *(__half2*)&k2s[r][c4]     = __floats2half2_rn(v.x, v.y);
            *(__half2*)&k2s[r][c4 + 2] = __floats2half2_rn(v.z, v.w);
        }
        for (int l = tid; l < 3200; l += 256) {        // 32 rows x 100 half2
            int r = l / 100, c = l - r*100;
            *(unsigned*)&Qtab[r][c*2] = 0u;
        }
    }
    __syncthreads();

    float zacc = 0.f;

    for (int isub = 0; isub < 4; ++isub) {
        const int il = isub*8 + w;
        const int ig = i0 + il;

        // A fragments: W[j,d] = q[i,d]*k1[j,d] (fp16), amortized over chunks
        unsigned afr[2][4][4];
        #pragma unroll
        for (int mt = 0; mt < 2; ++mt) {
            const int jlo = mt*16 + g, jhi = jlo + 8;
            #pragma unroll
            for (int ks = 0; ks < 4; ++ks) {
                const int d0 = ks*16 + q2;
                float qa = qs[il][d0],   qb = qs[il][d0+1];
                float qc = qs[il][d0+8], qd = qs[il][d0+9];
                afr[mt][ks][0] = pkh2(qa*k1s[jlo][d0],   qb*k1s[jlo][d0+1]);
                afr[mt][ks][1] = pkh2(qa*k1s[jhi][d0],   qb*k1s[jhi][d0+1]);
                afr[mt][ks][2] = pkh2(qc*k1s[jlo][d0+8], qd*k1s[jlo][d0+9]);
                afr[mt][ks][3] = pkh2(qc*k1s[jhi][d0+8], qd*k1s[jhi][d0+9]);
            }
        }

        for (int kc = 0; kc <= tj; ++kc) {
            const int n0 = kc * 32;
            const bool mk = (kc == tj);
            if (diag) {
                if (mk) do_chunk<true ,true >(n0, ig, il, j0, g, q2, lane, afr, k2s, Qtab, zacc);
                else    do_chunk<true ,false>(n0, ig, il, j0, g, q2, lane, afr, k2s, Qtab, zacc);
            } else {
                if (mk) do_chunk<false,true >(n0, ig, il, j0, g, q2, lane, afr, k2s, Qtab, zacc);
                else    do_chunk<false,false>(n0, ig, il, j0, g, q2, lane, afr, k2s, Qtab, zacc);
            }
        }
    }
    __syncthreads();

    // ---- PV: Np[32i, 64d] = Qtab[32i, K] @ k2[K, 64d] (one block GEMM) ----
    {
        const int gi = w & 1;           // i-group (16 rows)
        const int dt = w >> 1;          // d-tiles dt*8 and dt*8+32
        const int r0 = gi*16 + g;
        float pacc[2][4];
        #pragma unroll
        for (int t2 = 0; t2 < 2; ++t2)
            pacc[t2][0] = pacc[t2][1] = pacc[t2][2] = pacc[t2][3] = 0.f;

        for (int ks = 0; ks < K; ks += 16) {
            unsigned afrag[4];
            afrag[0] = *(const unsigned*)&Qtab[r0    ][ks + q2];
            afrag[1] = *(const unsigned*)&Qtab[r0 + 8][ks + q2];
            afrag[2] = *(const unsigned*)&Qtab[r0    ][ks + 8 + q2];
            afrag[3] = *(const unsigned*)&Qtab[r0 + 8][ks + 8 + q2];
            #pragma unroll
            for (int t2 = 0; t2 < 2; ++t2) {
                const int d0 = dt*8 + t2*32;
                unsigned b0, b1;
                ldsm_x2_trans(b0, b1, su32(&k2s[ks + (lane & 15)][d0]));
                unsigned bfrag[2] = {b0, b1};
                mma16816(pacc[t2], afrag, bfrag);
            }
        }
        float* np = g_Np + ((tj*BH + bh)*TT + i0)*HD;
        #pragma unroll
        for (int t2 = 0; t2 < 2; ++t2) {
            const int d0 = dt*8 + t2*32 + q2;
            *(float2*)&np[(r0    )*HD + d0] = make_float2(pacc[t2][0], pacc[t2][1]);
            *(float2*)&np[(r0 + 8)*HD + d0] = make_float2(pacc[t2][2], pacc[t2][3]);
        }
    }

    // Z partial: block-reduce
    #pragma unroll
    for (int m = 16; m >= 1; m >>= 1)
        zacc += __shfl_xor_sync(0xffffffffu, zacc, m);
    if (lane == 0) zred[w] = zacc;
    __syncthreads();
    if (tid == 0) {
        float z = 0.f;
        #pragma unroll
        for (int ww = 0; ww < 8; ++ww) z += zred[ww];
        g_Zp[bh*NPAIR + p] = z;
    }
}

// ---------------------------------------------------------------------------
// y = (sum of valid slab partials)/Z, written PACKED split-fp16 for out GEMM
__global__ __launch_bounds__(256)
void finalize_y()
{
    __shared__ float invZ[BH];
    const int tid = threadIdx.x;
    if (tid < BH) {
        float z = 0.f;
        #pragma unroll
        for (int pp = 0; pp < NPAIR; ++pp) z += g_Zp[tid*NPAIR + pp];
        invZ[tid] = 1.f / z;
    }
    __syncthreads();
    int e  = blockIdx.x * 256 + tid;    // < XN/4 = 49152
    int c4 = e & 127;
    int r  = e >> 7;
    int b = r / TT, t = r - b*TT;
    int h = c4 >> 4, d4 = c4 & 15;
    int bh = b*NH + h;
    float4 acc = make_float4(0.f, 0.f, 0.f, 0.f);
    const int smax = t >> 5;
    #pragma unroll
    for (int s = 0; s < NTILE; ++s) {      // unrolled + predicated -> MLP 6
        if (s <= smax) {
            float4 v = *(const float4*)&g_Np[((s*BH + bh)*TT + t)*HD + d4*4];
            acc.x += v.x; acc.y += v.y; acc.z += v.z; acc.w += v.w;
        }
    }
    float iz = invZ[bh];
    uint4 u;
    u.x = splitpack(acc.x * iz); u.y = splitpack(acc.y * iz);
    u.z = splitpack(acc.z * iz); u.w = splitpack(acc.w * iz);
    *(uint4*)&g_ys[r*CC + c4*4] = u;
}

// ---------------------------------------------------------------------------
// out partials: K-split halves of y @ Wp^T
__global__ __launch_bounds__(256)
void out_kernel()
{
    __shared__ __align__(16) unsigned sA[64][68];
    __shared__ __align__(16) unsigned sB[64][68];
    const int row0 = blockIdx.y * 64, col0 = blockIdx.x * 64;
    const int z = blockIdx.z;
    float acc[2][2][4];
    #pragma unroll
    for (int a = 0; a < 2; ++a)
        #pragma unroll
        for (int b = 0; b < 2; ++b)
            #pragma unroll
            for (int c = 0; c < 4; ++c) acc[a][b][c] = 0.f;
    gemm64_core(g_ys, g_Ws[3], row0, col0, z*(CC/2), (z+1)*(CC/2), acc, sA, sB);

    const int w = threadIdx.x >> 5, l = threadIdx.x & 31;
    const int wm = w >> 2, wn = w & 3;
    float* op = g_outp[z];
    #pragma unroll
    for (int mt = 0; mt < 2; ++mt)
        #pragma unroll
        for (int nt = 0; nt < 2; ++nt) {
            const int col = col0 + wn*16 + nt*8 + ((l & 3) << 1);
            #pragma unroll
            for (int rh = 0; rh < 2; ++rh) {
                const int row = row0 + wm*32 + mt*16 + (l >> 2) + rh*8;
                float2 v = make_float2(acc[mt][nt][rh*2], acc[mt][nt][rh*2 + 1]);
                *(float2*)&op[row*CC + col] = v;
            }
        }
}

// ---------------------------------------------------------------------------
__global__ __launch_bounds__(256)
void reduce_out(float* __restrict__ out)
{
    int e4 = (blockIdx.x * 256 + threadIdx.x) * 4;   // < XN
    float4 a = *(const float4*)&g_outp[0][e4];
    float4 b = *(const float4*)&g_outp[1][e4];
    float4 r = make_float4(a.x + b.x, a.y + b.y, a.z + b.z, a.w + b.w);
    *(float4*)&out[e4] = r;
}

// ---------------------------------------------------------------------------
extern "C" void kernel_launch(void* const* d_in, const int* in_sizes, int n_in,
                              void* d_out, int out_size)
{
    const float* x  = (const float*)d_in[0];
    const float* W0 = (const float*)d_in[1];
    const float* W1 = (const float*)d_in[2];
    const float* W2 = (const float*)d_in[3];
    const float* Wp = (const float*)d_in[4];
    float* out = (float*)d_out;

    cudaFuncSetAttribute(attn_kernel, cudaFuncAttributeMaxDynamicSharedMemorySize, SM_ATTN);

    cvt_main<<<(XN + 3*WN)/(256*4), 256>>>(x, W0, W1, W2);     // launch 1
    cvt_wp<<<WN/(256*4), 256>>>(Wp);                            // launch 2
    dim3 pg(CC/64, (BB*TT)/64, 3);
    proj_kernel<<<pg, 256>>>();                                 // launch 3
    attn_kernel<<<NPAIR*BH, 256, SM_ATTN>>>();                  // launch 4 (profiled)
    finalize_y<<<(XN/4)/256, 256>>>();
    dim3 og(CC/64, (BB*TT)/64, 2);
    out_kernel<<<og, 256>>>();
    reduce_out<<<(XN/4)/256, 256>>>(out);
}

// round 10
// speedup vs baseline: 1.2258x; 1.1004x over previous
#include <cuda_runtime.h>
#include <cuda_fp16.h>
#include <stdint.h>

#define BB 2
#define NH 8
#define TT 192
#define HD 64
#define CC 512
#define BH 16            // BB*NH
#define NTILE 6          // TT/32
#define NPAIR 21         // NTILE*(NTILE+1)/2
#define QPRE 0.18033688f // 0.125 * log2(e): exp(S/8) = exp2(S*QPRE)
#define XN (BB*TT*CC)    // 196608
#define WN (CC*CC)       // 262144

// attn dynamic smem layout (bytes)
#define SM_K2S   0                       // __half[192][72] = 27648
#define SM_QS    27648                   // float [32][65]  = 8320
#define SM_K1S   35968                   // float [32][65]  = 8320
#define SM_QTAB  44288                   // __half[32][200] = 12800
#define SM_ZRED  57088                   // float[8]        = 32
#define SM_ATTN  57344

// persistent device scratch (no allocations allowed)
__device__ __align__(16) float    g_q [BH*TT*HD];
__device__ __align__(16) float    g_k1[BH*TT*HD];
__device__ __align__(16) float    g_k2[BH*TT*HD];
__device__ __align__(16) float    g_Np[NTILE*BH*TT*HD];
__device__ __align__(16) float    g_Zp[BH*NPAIR];
__device__ __align__(16) unsigned g_xs[XN];        // x packed split-fp16
__device__ __align__(16) unsigned g_Ws[4][WN];     // W0,W1,W2,Wp packed
__device__ __align__(16) unsigned g_ys[XN];        // normalized y packed
__device__ __align__(16) float    g_outp[2][XN];   // out K-split partials

// ---------------------------------------------------------------------------
// HMMA helpers
__device__ __forceinline__ unsigned int pkh2(float a, float b)
{
    __half2 h = __floats2half2_rn(a, b);
    return *reinterpret_cast<unsigned int*>(&h);
}

__device__ __forceinline__ void mma16816(float* d, const unsigned int* a, const unsigned int* b)
{
    asm volatile(
        "mma.sync.aligned.m16n8k16.row.col.f32.f16.f16.f32 "
        "{%0,%1,%2,%3}, {%4,%5,%6,%7}, {%8,%9}, {%0,%1,%2,%3};\n"
        : "+f"(d[0]), "+f"(d[1]), "+f"(d[2]), "+f"(d[3])
        : "r"(a[0]), "r"(a[1]), "r"(a[2]), "r"(a[3]), "r"(b[0]), "r"(b[1]));
}

__device__ __forceinline__ void ldsm_x2_trans(unsigned& r0, unsigned& r1, unsigned addr)
{
    asm volatile("ldmatrix.sync.aligned.m8n8.x2.trans.shared.b16 {%0,%1}, [%2];"
        : "=r"(r0), "=r"(r1) : "r"(addr));
}

__device__ __forceinline__ void ldsm_x4(unsigned& r0, unsigned& r1, unsigned& r2,
                                        unsigned& r3, unsigned addr)
{
    asm volatile("ldmatrix.sync.aligned.m8n8.x4.shared.b16 {%0,%1,%2,%3}, [%4];"
        : "=r"(r0), "=r"(r1), "=r"(r2), "=r"(r3) : "r"(addr));
}

__device__ __forceinline__ unsigned su32(const void* p)
{
    return (unsigned)__cvta_generic_to_shared(p);
}

// bare MUFU exp2 (exp2f without fast-math is a ~18-instr softfloat routine!)
__device__ __forceinline__ float ex2(float x)
{
    float y;
    asm("ex2.approx.ftz.f32 %0, %1;" : "=f"(y) : "f"(x));
    return y;
}

// pack value as (hi fp16) | (lo fp16 << 16); hi+lo ~ 22-bit mantissa of f
__device__ __forceinline__ unsigned int splitpack(float f)
{
    __half h = __float2half_rn(f);
    __half l = __float2half_rn(f - __half2float(h));
    return (unsigned int)__half_as_ushort(h) | ((unsigned int)__half_as_ushort(l) << 16);
}

// ---------------------------------------------------------------------------
// convert x + W0..W2 to packed split-fp16 (float4-vectorized)
__global__ __launch_bounds__(256)
void cvt_main(const float* __restrict__ x,  const float* __restrict__ W0,
              const float* __restrict__ W1, const float* __restrict__ W2)
{
    int i4 = (blockIdx.x * 256 + threadIdx.x) * 4;   // 960 blocks: XN + 3*WN
    const float* src;
    unsigned*    dst;
    if (i4 < XN) {
        src = x + i4;
        dst = g_xs + i4;
    } else {
        int o = i4 - XN;
        int r = o >> 18;          // WN = 2^18
        o &= (WN - 1);
        src = (r == 0 ? W0 : r == 1 ? W1 : W2) + o;
        dst = g_Ws[r] + o;
    }
    float4 v = *(const float4*)src;
    uint4 u;
    u.x = splitpack(v.x); u.y = splitpack(v.y);
    u.z = splitpack(v.z); u.w = splitpack(v.w);
    *(uint4*)dst = u;
}

// convert Wp (separate launch — keeps attn in the ncu-profiled slot #4)
__global__ __launch_bounds__(256)
void cvt_wp(const float* __restrict__ Wp)
{
    int i4 = (blockIdx.x * 256 + threadIdx.x) * 4;   // 256 blocks: WN
    float4 v = *(const float4*)(Wp + i4);
    uint4 u;
    u.x = splitpack(v.x); u.y = splitpack(v.y);
    u.z = splitpack(v.z); u.w = splitpack(v.w);
    *(uint4*)&g_Ws[3][i4] = u;
}

// ---------------------------------------------------------------------------
// split-fp16 GEMM core on pre-packed operands (row stride 68 = 16B-aligned rows)
__device__ __forceinline__ void gemm64_core(
    const unsigned* __restrict__ A, const unsigned* __restrict__ B,
    int row0, int col0, int kb, int ke, float (&acc)[2][2][4],
    unsigned (*sA)[68], unsigned (*sB)[68])
{
    const int tid = threadIdx.x;
    const int w  = tid >> 5, l = tid & 31;
    const int wm = w >> 2, wn = w & 3;
    const int g  = l >> 2, c2 = (l & 3) << 1;
    const int lr = tid >> 2, lc0 = (tid & 3) << 4;

    for (int kc = kb; kc < ke; kc += 64) {
        const unsigned* ap = A + (row0 + lr)*CC + kc + lc0;
        const unsigned* bp = B + (col0 + lr)*CC + kc + lc0;
        #pragma unroll
        for (int v = 0; v < 4; ++v) {
            *(uint4*)&sA[lr][lc0 + v*4] = *(const uint4*)(ap + v*4);
            *(uint4*)&sB[lr][lc0 + v*4] = *(const uint4*)(bp + v*4);
        }
        __syncthreads();
        #pragma unroll
        for (int ks = 0; ks < 4; ++ks) {
            const int k0 = ks*16 + c2;
            unsigned ahi[2][4], alo[2][4];
            #pragma unroll
            for (int mt = 0; mt < 2; ++mt) {
                const int r = wm*32 + mt*16 + g;
                uint2 p0 = *(const uint2*)&sA[r    ][k0    ];
                uint2 p1 = *(const uint2*)&sA[r + 8][k0    ];
                uint2 p2 = *(const uint2*)&sA[r    ][k0 + 8];
                uint2 p3 = *(const uint2*)&sA[r + 8][k0 + 8];
                ahi[mt][0] = __byte_perm(p0.x, p0.y, 0x5410);
                alo[mt][0] = __byte_perm(p0.x, p0.y, 0x7632);
                ahi[mt][1] = __byte_perm(p1.x, p1.y, 0x5410);
                alo[mt][1] = __byte_perm(p1.x, p1.y, 0x7632);
                ahi[mt][2] = __byte_perm(p2.x, p2.y, 0x5410);
                alo[mt][2] = __byte_perm(p2.x, p2.y, 0x7632);
                ahi[mt][3] = __byte_perm(p3.x, p3.y, 0x5410);
                alo[mt][3] = __byte_perm(p3.x, p3.y, 0x7632);
            }
            #pragma unroll
            for (int nt = 0; nt < 2; ++nt) {
                const int n = wn*16 + nt*8 + g;
                uint2 q0 = *(const uint2*)&sB[n][k0    ];
                uint2 q1 = *(const uint2*)&sB[n][k0 + 8];
                unsigned bhi[2], blo[2];
                bhi[0] = __byte_perm(q0.x, q0.y, 0x5410);
                blo[0] = __byte_perm(q0.x, q0.y, 0x7632);
                bhi[1] = __byte_perm(q1.x, q1.y, 0x5410);
                blo[1] = __byte_perm(q1.x, q1.y, 0x7632);
                #pragma unroll
                for (int mt = 0; mt < 2; ++mt) {
                    mma16816(acc[mt][nt], ahi[mt], bhi);
                    mma16816(acc[mt][nt], ahi[mt], blo);
                    mma16816(acc[mt][nt], alo[mt], bhi);
                }
            }
        }
        __syncthreads();
    }
}

// ---------------------------------------------------------------------------
// projections: q = x@W0^T, k1 = x@W1^T, k2 = x@W2^T, stored [bh][t][d]
__global__ __launch_bounds__(256)
void proj_kernel()
{
    __shared__ __align__(16) unsigned sA[64][68];
    __shared__ __align__(16) unsigned sB[64][68];
    float* dst = (blockIdx.z == 0) ? g_q : (blockIdx.z == 1) ? g_k1 : g_k2;
    const int row0 = blockIdx.y * 64, col0 = blockIdx.x * 64;
    float acc[2][2][4];
    #pragma unroll
    for (int a = 0; a < 2; ++a)
        #pragma unroll
        for (int b = 0; b < 2; ++b)
            #pragma unroll
            for (int c = 0; c < 4; ++c) acc[a][b][c] = 0.f;
    gemm64_core(g_xs, g_Ws[blockIdx.z], row0, col0, 0, CC, acc, sA, sB);

    const int w = threadIdx.x >> 5, l = threadIdx.x & 31;
    const int wm = w >> 2, wn = w & 3;
    #pragma unroll
    for (int mt = 0; mt < 2; ++mt)
        #pragma unroll
        for (int nt = 0; nt < 2; ++nt) {
            const int col = col0 + wn*16 + nt*8 + ((l & 3) << 1);
            const int h = col >> 6, d = col & 63;
            #pragma unroll
            for (int rh = 0; rh < 2; ++rh) {
                const int row = row0 + wm*32 + mt*16 + (l >> 2) + rh*8;
                const int b = row / TT, t = row - b*TT;
                float2 v = make_float2(acc[mt][nt][rh*2], acc[mt][nt][rh*2 + 1]);
                *(float2*)&dst[((b*NH + h)*TT + t)*HD + d] = v;
            }
        }
}

// ---------------------------------------------------------------------------
// one 32-token k-chunk: score MMA + ex2 + j-fold -> Qtab row (no PV here).
// bbase: ldmatrix lane address for this chunk's nt=0 token group.
template<bool MJ, bool MK>
__device__ __forceinline__ void do_chunk(
    int n0, int ig, int il, int j0, int g, int q2, int lane, unsigned bbase,
    const unsigned (&afr)[2][4][4], __half (*Qtab)[200], float& zacc)
{
    #pragma unroll
    for (int nt = 0; nt < 4; ++nt) {
        if (MJ && MK && (n0 + nt*8) > ig) continue;   // fully-masked token group
        // B fragments via 2x ldmatrix.x4 (8 tiles: 4 ks x 2 k-halves)
        unsigned bfr[4][2];
        {
            unsigned a0 = bbase + nt*(8*144);          // +8 token rows
            ldsm_x4(bfr[0][0], bfr[0][1], bfr[1][0], bfr[1][1], a0);
            ldsm_x4(bfr[2][0], bfr[2][1], bfr[3][0], bfr[3][1], a0 + 64);
        }
        float Qf0 = 0.f, Qf1 = 0.f;
        #pragma unroll
        for (int mt = 0; mt < 2; ++mt) {
            if (MJ && (j0 + mt*16) > ig) continue;    // whole 16-row group above i
            float acc[4] = {0.f, 0.f, 0.f, 0.f};
            #pragma unroll
            for (int ks = 0; ks < 4; ++ks) mma16816(acc, afr[mt][ks], bfr[ks]);
            const int jlo = j0 + mt*16 + g, jhi = jlo + 8;
            const int k0  = n0 + nt*8 + q2, k1 = k0 + 1;
            bool v0 = (!MJ || jlo <= ig) && (!MK || k0 <= jlo);
            bool v1 = (!MJ || jlo <= ig) && (!MK || k1 <= jlo);
            bool v2 = (!MJ || jhi <= ig) && (!MK || k0 <= jhi);
            bool v3 = (!MJ || jhi <= ig) && (!MK || k1 <= jhi);
            float p0 = v0 ? ex2(acc[0]) : 0.f;        // scale pre-folded into q
            float p1 = v1 ? ex2(acc[1]) : 0.f;
            float p2 = v2 ? ex2(acc[2]) : 0.f;
            float p3 = v3 ? ex2(acc[3]) : 0.f;
            Qf0 += p0 + p2;
            Qf1 += p1 + p3;
        }
        // fold across the 8 j row-groups (lanes differing in bits 2..4)
        #pragma unroll
        for (int m = 4; m <= 16; m <<= 1) {
            Qf0 += __shfl_xor_sync(0xffffffffu, Qf0, m);
            Qf1 += __shfl_xor_sync(0xffffffffu, Qf1, m);
        }
        zacc += (Qf0 + Qf1) * 0.125f;                 // 8-lane replication
        unsigned qp = pkh2(Qf0, Qf1);
        if (lane < 4)                                  // lanes 0..3 cover 8 tokens
            *(unsigned*)&Qtab[il][n0 + nt*8 + (lane << 1)] = qp;
    }
}

// ---------------------------------------------------------------------------
// fused trilinear scores (HMMA) + ex2 + j-fold -> Qtab; PV as one block GEMM.
__global__ __launch_bounds__(256, 3)
void attn_kernel()
{
    extern __shared__ char dynsm[];
    __half (*k2s)[72]  = (__half(*)[72]) (dynsm + SM_K2S);
    float  (*qs)[65]   = (float(*)[65])  (dynsm + SM_QS);
    float  (*k1s)[65]  = (float(*)[65])  (dynsm + SM_K1S);
    __half (*Qtab)[200]= (__half(*)[200])(dynsm + SM_QTAB);
    float* zred        = (float*)        (dynsm + SM_ZRED);

    const int bh = blockIdx.x & 15;
    const int p  = blockIdx.x >> 4;
    int tj = NTILE - 1, start = 0, cnt = 1;
    while (p >= start + cnt) { start += cnt; --tj; ++cnt; }
    const int ti = tj + (p - start);
    const int i0 = ti * 32, j0 = tj * 32;
    const int tid  = threadIdx.x;
    const int w    = tid >> 5, lane = tid & 31;
    const int g    = lane >> 2, q2 = (lane & 3) << 1;
    const bool diag = (ti == tj);
    const int K = (tj + 1) * 32;

    // ldmatrix lane base for chunk kc=0, nt=0 (row = token lane&7, col tile lane>>3)
    const unsigned bmat0 = su32(dynsm + SM_K2S) + (lane & 7)*144 + (lane >> 3)*16;

    // load q (prescaled by QPRE) / k1 fp32; k2 fp16; zero Qtab
    {
        const float* qg  = g_q  + (bh*TT + i0)*HD;
        const float* k1g = g_k1 + (bh*TT + j0)*HD;
        for (int l = tid; l < 32*64; l += 256) {
            int r = l >> 6, d = l & 63;
            qs[r][d]  = qg[r*HD + d] * QPRE;
            k1s[r][d] = k1g[r*HD + d];
        }
        const float* k2g = g_k2 + bh*TT*HD;
        for (int l = tid; l < K*16; l += 256) {
            int r = l >> 4, c4 = (l & 15) << 2;
            float4 v = *(const float4*)(k2g + r*HD + c4);
            *(__half2*)&k2s[r][c4]     = __floats2half2_rn(v.x, v.y);
            *(__half2*)&k2s[r][c4 + 2] = __floats2half2_rn(v.z, v.w);
        }
        for (int l = tid; l < 3200; l += 256) {        // 32 rows x 100 half2
            int r = l / 100, c = l - r*100;
            *(unsigned*)&Qtab[r][c*2] = 0u;
        }
    }
    __syncthreads();

    float zacc = 0.f;

    for (int isub = 0; isub < 4; ++isub) {
        const int il = isub*8 + w;
        const int ig = i0 + il;

        // A fragments: W[j,d] = q[i,d]*k1[j,d] (fp16), amortized over chunks
        unsigned afr[2][4][4];
        #pragma unroll
        for (int mt = 0; mt < 2; ++mt) {
            const int jlo = mt*16 + g, jhi = jlo + 8;
            #pragma unroll
            for (int ks = 0; ks < 4; ++ks) {
                const int d0 = ks*16 + q2;
                float qa = qs[il][d0],   qb = qs[il][d0+1];
                float qc = qs[il][d0+8], qd = qs[il][d0+9];
                afr[mt][ks][0] = pkh2(qa*k1s[jlo][d0],   qb*k1s[jlo][d0+1]);
                afr[mt][ks][1] = pkh2(qa*k1s[jhi][d0],   qb*k1s[jhi][d0+1]);
                afr[mt][ks][2] = pkh2(qc*k1s[jlo][d0+8], qd*k1s[jlo][d0+9]);
                afr[mt][ks][3] = pkh2(qc*k1s[jhi][d0+8], qd*k1s[jhi][d0+9]);
            }
        }

        for (int kc = 0; kc <= tj; ++kc) {
            const int n0 = kc * 32;
            const unsigned bb = bmat0 + n0*144;
            const bool mk = (kc == tj);
            if (diag) {
                if (mk) do_chunk<true ,true >(n0, ig, il, j0, g, q2, lane, bb, afr, Qtab, zacc);
                else    do_chunk<true ,false>(n0, ig, il, j0, g, q2, lane, bb, afr, Qtab, zacc);
            } else {
                if (mk) do_chunk<false,true >(n0, ig, il, j0, g, q2, lane, bb, afr, Qtab, zacc);
                else    do_chunk<false,false>(n0, ig, il, j0, g, q2, lane, bb, afr, Qtab, zacc);
            }
        }
    }
    __syncthreads();

    // ---- PV: Np[32i, 64d] = Qtab[32i, K] @ k2[K, 64d] (one block GEMM) ----
    {
        const int gi = w & 1;           // i-group (16 rows)
        const int dt = w >> 1;          // d-tiles dt*8 and dt*8+32
        const int r0 = gi*16 + g;
        float pacc[2][4];
        #pragma unroll
        for (int t2 = 0; t2 < 2; ++t2)
            pacc[t2][0] = pacc[t2][1] = pacc[t2][2] = pacc[t2][3] = 0.f;

        for (int ks = 0; ks < K; ks += 16) {
            unsigned afrag[4];
            afrag[0] = *(const unsigned*)&Qtab[r0    ][ks + q2];
            afrag[1] = *(const unsigned*)&Qtab[r0 + 8][ks + q2];
            afrag[2] = *(const unsigned*)&Qtab[r0    ][ks + 8 + q2];
            afrag[3] = *(const unsigned*)&Qtab[r0 + 8][ks + 8 + q2];
            #pragma unroll
            for (int t2 = 0; t2 < 2; ++t2) {
                const int d0 = dt*8 + t2*32;
                unsigned b0, b1;
                ldsm_x2_trans(b0, b1, su32(&k2s[ks + (lane & 15)][d0]));
                unsigned bfrag[2] = {b0, b1};
                mma16816(pacc[t2], afrag, bfrag);
            }
        }
        float* np = g_Np + ((tj*BH + bh)*TT + i0)*HD;
        #pragma unroll
        for (int t2 = 0; t2 < 2; ++t2) {
            const int d0 = dt*8 + t2*32 + q2;
            *(float2*)&np[(r0    )*HD + d0] = make_float2(pacc[t2][0], pacc[t2][1]);
            *(float2*)&np[(r0 + 8)*HD + d0] = make_float2(pacc[t2][2], pacc[t2][3]);
        }
    }

    // Z partial: block-reduce
    #pragma unroll
    for (int m = 16; m >= 1; m >>= 1)
        zacc += __shfl_xor_sync(0xffffffffu, zacc, m);
    if (lane == 0) zred[w] = zacc;
    __syncthreads();
    if (tid == 0) {
        float z = 0.f;
        #pragma unroll
        for (int ww = 0; ww < 8; ++ww) z += zred[ww];
        g_Zp[bh*NPAIR + p] = z;
    }
}

// ---------------------------------------------------------------------------
// y = (sum of valid slab partials)/Z, written PACKED split-fp16 for out GEMM
__global__ __launch_bounds__(256)
void finalize_y()
{
    __shared__ float invZ[BH];
    const int tid = threadIdx.x;
    if (tid < BH) {
        float z = 0.f;
        #pragma unroll
        for (int pp = 0; pp < NPAIR; ++pp) z += g_Zp[tid*NPAIR + pp];
        invZ[tid] = 1.f / z;
    }
    __syncthreads();
    int e  = blockIdx.x * 256 + tid;    // < XN/4 = 49152
    int c4 = e & 127;
    int r  = e >> 7;
    int b = r / TT, t = r - b*TT;
    int h = c4 >> 4, d4 = c4 & 15;
    int bh = b*NH + h;
    float4 acc = make_float4(0.f, 0.f, 0.f, 0.f);
    const int smax = t >> 5;
    #pragma unroll
    for (int s = 0; s < NTILE; ++s) {      // unrolled + predicated -> MLP 6
        if (s <= smax) {
            float4 v = *(const float4*)&g_Np[((s*BH + bh)*TT + t)*HD + d4*4];
            acc.x += v.x; acc.y += v.y; acc.z += v.z; acc.w += v.w;
        }
    }
    float iz = invZ[bh];
    uint4 u;
    u.x = splitpack(acc.x * iz); u.y = splitpack(acc.y * iz);
    u.z = splitpack(acc.z * iz); u.w = splitpack(acc.w * iz);
    *(uint4*)&g_ys[r*CC + c4*4] = u;
}

// ---------------------------------------------------------------------------
// out partials: K-split halves of y @ Wp^T
__global__ __launch_bounds__(256)
void out_kernel()
{
    __shared__ __align__(16) unsigned sA[64][68];
    __shared__ __align__(16) unsigned sB[64][68];
    const int row0 = blockIdx.y * 64, col0 = blockIdx.x * 64;
    const int z = blockIdx.z;
    float acc[2][2][4];
    #pragma unroll
    for (int a = 0; a < 2; ++a)
        #pragma unroll
        for (int b = 0; b < 2; ++b)
            #pragma unroll
            for (int c = 0; c < 4; ++c) acc[a][b][c] = 0.f;
    gemm64_core(g_ys, g_Ws[3], row0, col0, z*(CC/2), (z+1)*(CC/2), acc, sA, sB);

    const int w = threadIdx.x >> 5, l = threadIdx.x & 31;
    const int wm = w >> 2, wn = w & 3;
    float* op = g_outp[z];
    #pragma unroll
    for (int mt = 0; mt < 2; ++mt)
        #pragma unroll
        for (int nt = 0; nt < 2; ++nt) {
            const int col = col0 + wn*16 + nt*8 + ((l & 3) << 1);
            #pragma unroll
            for (int rh = 0; rh < 2; ++rh) {
                const int row = row0 + wm*32 + mt*16 + (l >> 2) + rh*8;
                float2 v = make_float2(acc[mt][nt][rh*2], acc[mt][nt][rh*2 + 1]);
                *(float2*)&op[row*CC + col] = v;
            }
        }
}

// ---------------------------------------------------------------------------
__global__ __launch_bounds__(256)
void reduce_out(float* __restrict__ out)
{
    int e4 = (blockIdx.x * 256 + threadIdx.x) * 4;   // < XN
    float4 a = *(const float4*)&g_outp[0][e4];
    float4 b = *(const float4*)&g_outp[1][e4];
    float4 r = make_float4(a.x + b.x, a.y + b.y, a.z + b.z, a.w + b.w);
    *(float4*)&out[e4] = r;
}

// ---------------------------------------------------------------------------
extern "C" void kernel_launch(void* const* d_in, const int* in_sizes, int n_in,
                              void* d_out, int out_size)
{
    const float* x  = (const float*)d_in[0];
    const float* W0 = (const float*)d_in[1];
    const float* W1 = (const float*)d_in[2];
    const float* W2 = (const float*)d_in[3];
    const float* Wp = (const float*)d_in[4];
    float* out = (float*)d_out;

    cudaFuncSetAttribute(attn_kernel, cudaFuncAttributeMaxDynamicSharedMemorySize, SM_ATTN);

    cvt_main<<<(XN + 3*WN)/(256*4), 256>>>(x, W0, W1, W2);     // launch 1
    cvt_wp<<<WN/(256*4), 256>>>(Wp);                            // launch 2
    dim3 pg(CC/64, (BB*TT)/64, 3);
    proj_kernel<<<pg, 256>>>();                                 // launch 3
    attn_kernel<<<NPAIR*BH, 256, SM_ATTN>>>();                  // launch 4 (profiled)
    finalize_y<<<(XN/4)/256, 256>>>();
    dim3 og(CC/64, (BB*TT)/64, 2);
    out_kernel<<<og, 256>>>();
    reduce_out<<<(XN/4)/256, 256>>>(out);
}